// round 13
// baseline (speedup 1.0000x reference)
#include <cuda_runtime.h>
#include <cuda_bf16.h>
#include <cuda_fp16.h>
#include <cstdint>

#define N_NODES 50000
#define D 128
#define N_EDGES 625000
#define PREP_BLOCKS 128
#define XCONV_BLOCKS ((N_NODES * D / 8 + 255) / 256)   // 3125

// Device-global scratch (allocation-free rule; BSS zero-initialized)
__device__ __half g_xh[N_NODES * D];          // fp16 copy of x (gather source)
__device__ __half g_sumh[N_NODES * D];        // fp16 edge-sum accumulator (re-zeroed by gemm)
__device__ float g_deg[N_NODES];              // re-zeroed by inv each run
__device__ float g_inv[N_NODES];
__device__ __nv_bfloat16 g_W[4 * 128 * 128];  // Wl_hi, Wl_lo, Wr_hi, Wr_lo  [mat][k][n]

// ---------------------------------------------------------------------------
// helpers
// ---------------------------------------------------------------------------
__device__ __forceinline__ uint32_t smem_u32(const void* p) {
    uint32_t a;
    asm("{ .reg .u64 t; cvta.to.shared.u64 t, %1; cvt.u32.u64 %0, t; }" : "=r"(a) : "l"(p));
    return a;
}

#define CP_ASYNC16(dst, src) \
    asm volatile("cp.async.cg.shared.global [%0], [%1], 16;" :: "r"(dst), "l"(src))
#define CP_COMMIT() asm volatile("cp.async.commit_group;")
#define CP_WAIT0()  asm volatile("cp.async.wait_group 0;" ::: "memory")

#define LDSM_X4(r, addr) \
    asm volatile("ldmatrix.sync.aligned.m8n8.x4.shared.b16 {%0,%1,%2,%3}, [%4];" \
                 : "=r"((r)[0]), "=r"((r)[1]), "=r"((r)[2]), "=r"((r)[3]) : "r"(addr))
#define LDSM_X4T(r, addr) \
    asm volatile("ldmatrix.sync.aligned.m8n8.x4.trans.shared.b16 {%0,%1,%2,%3}, [%4];" \
                 : "=r"((r)[0]), "=r"((r)[1]), "=r"((r)[2]), "=r"((r)[3]) : "r"(addr))

__device__ __forceinline__ void mma16816(float* d, const uint32_t* a, const uint32_t* b) {
    asm volatile(
        "mma.sync.aligned.m16n8k16.row.col.f32.bf16.bf16.f32 "
        "{%0,%1,%2,%3}, {%4,%5,%6,%7}, {%8,%9}, {%0,%1,%2,%3};"
        : "+f"(d[0]), "+f"(d[1]), "+f"(d[2]), "+f"(d[3])
        : "r"(a[0]), "r"(a[1]), "r"(a[2]), "r"(a[3]), "r"(b[0]), "r"(b[1]));
}

__device__ __forceinline__ uint32_t pack_bf16x2(float a, float b) {
    __nv_bfloat16 ha = __float2bfloat16(a), hb = __float2bfloat16(b);
    return (uint32_t)__bfloat16_as_ushort(ha) | ((uint32_t)__bfloat16_as_ushort(hb) << 16);
}

__device__ __forceinline__ uint32_t h2u(__half2 h) {
    uint32_t u;
    __builtin_memcpy(&u, &h, 4);
    return u;
}

// ---------------------------------------------------------------------------
// 1. fused: weight prep (blocks 0..127) + x -> fp16 conversion (rest).
// ---------------------------------------------------------------------------
__global__ void conv_prep(const float* __restrict__ x,
                          const float* __restrict__ Wl,
                          const float* __restrict__ Wr) {
    int tid = threadIdx.x;
    if (blockIdx.x < PREP_BLOCKS) {
        int idx = blockIdx.x * 256 + tid;        // 0..32767
        int m2 = idx >> 14;
        int k  = (idx >> 7) & 127;
        int n  = idx & 127;
        float w = (m2 ? Wr : Wl)[k * 128 + n];
        __nv_bfloat16 h = __float2bfloat16(w);
        __nv_bfloat16 l = __float2bfloat16(w - __bfloat162float(h));
        g_W[(m2 * 2 + 0) * 16384 + k * 128 + n] = h;
        g_W[(m2 * 2 + 1) * 16384 + k * 128 + n] = l;
        return;
    }
    int i = ((int)blockIdx.x - PREP_BLOCKS) * 256 + tid;   // one 8-float chunk
    if (i >= N_NODES * D / 8) return;
    const float4* xs = reinterpret_cast<const float4*>(x) + i * 2;
    float4 a = xs[0], b = xs[1];
    uint4 o;
    o.x = h2u(__floats2half2_rn(a.x, a.y));
    o.y = h2u(__floats2half2_rn(a.z, a.w));
    o.z = h2u(__floats2half2_rn(b.x, b.y));
    o.w = h2u(__floats2half2_rn(b.z, b.w));
    reinterpret_cast<uint4*>(g_xh)[i] = o;
}

// ---------------------------------------------------------------------------
// 2. edge scatter: 16 lanes per edge (2 edges/warp). fp16 gather (16B/lane),
//    red.global.add.noftz.v4.f16x2 -> 16 red ops + 16 gather sectors per edge.
// ---------------------------------------------------------------------------
__global__ void scatter_kernel(const int* __restrict__ ei) {
    int warp = (blockIdx.x * blockDim.x + threadIdx.x) >> 5;
    int lane = threadIdx.x & 31;
    int li = lane & 15;
    int e = warp * 2 + (lane >> 4);
    if (e >= N_EDGES) return;
    int src = ei[e];
    int dst = ei[N_EDGES + e];

    uint4 v = reinterpret_cast<const uint4*>(g_xh + (size_t)src * D)[li];
    __half* dptr = g_sumh + (size_t)dst * D + li * 8;
    asm volatile("red.global.add.noftz.v4.f16x2 [%0], {%1, %2, %3, %4};"
                 :: "l"(dptr), "r"(v.x), "r"(v.y), "r"(v.z), "r"(v.w)
                 : "memory");
    if (li == 0) atomicAdd(g_deg + dst, 1.0f);
}

// ---------------------------------------------------------------------------
// 3. inverse degree; re-zeroes g_deg for the next replay
// ---------------------------------------------------------------------------
__global__ void inv_kernel() {
    int i = blockIdx.x * blockDim.x + threadIdx.x;
    if (i < N_NODES) {
        float d = g_deg[i];
        g_inv[i] = 1.0f / fmaxf(d, 1.0f);
        g_deg[i] = 0.0f;
    }
}

// ---------------------------------------------------------------------------
// 4. HMMA GEMM: out = x + relu([mean|x] @ [Wl;Wr] + b)
//    5-term: m_hi*(Wl_hi+Wl_lo) + x_hi*Wr_hi + x_lo*Wr_hi + x_hi*Wr_lo
//    A mats: m_hi, x_hi, x_lo. 64x128 tile/CTA, 2 CTAs/SM, 97KB smem.
// ---------------------------------------------------------------------------
#define ASTR 72
#define BSTR 136
#define A_MAT_B (64 * ASTR * 2)       // 9216 B
#define B_MAT_B (64 * BSTR * 2)       // 17408 B
#define SM_A_B (3 * A_MAT_B)          // 27648 B
#define SM_B_B (4 * B_MAT_B)          // 69632 B
#define SMEM_TOTAL (SM_A_B + SM_B_B)  // 97280 B -> 2 CTAs/SM

__global__ __launch_bounds__(256, 2)
void gemm_mma(const float* __restrict__ x,
              const float* __restrict__ bl,
              float* __restrict__ out) {
    extern __shared__ char sm[];
    const uint32_t sA = smem_u32(sm);
    const uint32_t sB = sA + SM_A_B;

    const int tid = threadIdx.x;
    const int lane = tid & 31;
    const int w = tid >> 5;
    const int m0 = blockIdx.x * 64;
    const int mrow0 = (w >> 1) * 16;
    const int ncol0 = (w & 1) * 64;

    float acc[8][4];
    #pragma unroll
    for (int nt = 0; nt < 8; nt++)
        #pragma unroll
        for (int q = 0; q < 4; q++) acc[nt][q] = 0.f;

    for (int c = 0; c < 2; c++) {
        const int k0 = c * 64;
        __syncthreads();    // previous chunk's MMAs done before smem overwrite

        // ---- B: 4 mats x 64k x 128n bf16 via cp.async ----
        #pragma unroll
        for (int i = 0; i < 16; i++) {
            int idx = tid + i * 256;          // 0..4095
            int mat = idx >> 10;
            int rem = idx & 1023;
            int r = rem >> 4, sg = rem & 15;
            uint32_t dst = sB + mat * B_MAT_B + r * (BSTR * 2) + sg * 16;
            const void* src = g_W + mat * 16384 + (k0 + r) * 128 + sg * 8;
            CP_ASYNC16(dst, src);
        }
        CP_COMMIT();

        // ---- A conversion: 4 threads per row, 16 cols each ----
        {
            int r = tid >> 2;                 // 0..63
            int part = tid & 3;
            int row = m0 + r;
            bool valid = row < N_NODES;
            float invd = valid ? g_inv[row] : 1.0f;

            // mean mat (0: hi only) from fp16 g_sumh * invd; re-zero after
            uint4* hp = valid
                ? reinterpret_cast<uint4*>(g_sumh + (size_t)row * D + k0 + part * 16)
                : nullptr;
            uint4 u0 = valid ? hp[0] : make_uint4(0, 0, 0, 0);
            uint4 u1 = valid ? hp[1] : make_uint4(0, 0, 0, 0);
            uint32_t h2s[8] = {u0.x, u0.y, u0.z, u0.w, u1.x, u1.y, u1.z, u1.w};
            uint32_t hi[8], lo[8];
            #pragma unroll
            for (int i = 0; i < 4; i++) {
                float2 fa = __half22float2(*reinterpret_cast<__half2*>(&h2s[2*i]));
                float2 fb = __half22float2(*reinterpret_cast<__half2*>(&h2s[2*i+1]));
                hi[2*i]   = pack_bf16x2(fa.x * invd, fa.y * invd);
                hi[2*i+1] = pack_bf16x2(fb.x * invd, fb.y * invd);
            }
            {
                uint4* dh = reinterpret_cast<uint4*>(sm + 0 * A_MAT_B + r * (ASTR * 2) + part * 32);
                dh[0] = make_uint4(hi[0], hi[1], hi[2], hi[3]);
                dh[1] = make_uint4(hi[4], hi[5], hi[6], hi[7]);
            }
            if (valid) {
                hp[0] = make_uint4(0, 0, 0, 0);   // re-zero fp16 sums for next replay
                hp[1] = make_uint4(0, 0, 0, 0);
            }

            // x mats (1: hi, 2: lo)
            const float4* xs = reinterpret_cast<const float4*>(
                x + (size_t)row * D + k0 + part * 16);
            #pragma unroll
            for (int i = 0; i < 4; i++) {
                float4 v = valid ? xs[i] : make_float4(0.f, 0.f, 0.f, 0.f);
                __nv_bfloat16 h0 = __float2bfloat16(v.x), h1 = __float2bfloat16(v.y);
                __nv_bfloat16 h2 = __float2bfloat16(v.z), h3 = __float2bfloat16(v.w);
                hi[2*i]   = (uint32_t)__bfloat16_as_ushort(h0) | ((uint32_t)__bfloat16_as_ushort(h1) << 16);
                hi[2*i+1] = (uint32_t)__bfloat16_as_ushort(h2) | ((uint32_t)__bfloat16_as_ushort(h3) << 16);
                lo[2*i]   = pack_bf16x2(v.x - __bfloat162float(h0), v.y - __bfloat162float(h1));
                lo[2*i+1] = pack_bf16x2(v.z - __bfloat162float(h2), v.w - __bfloat162float(h3));
            }
            {
                uint4* dh = reinterpret_cast<uint4*>(sm + 1 * A_MAT_B + r * (ASTR * 2) + part * 32);
                uint4* dl = reinterpret_cast<uint4*>(sm + 2 * A_MAT_B + r * (ASTR * 2) + part * 32);
                dh[0] = make_uint4(hi[0], hi[1], hi[2], hi[3]);
                dh[1] = make_uint4(hi[4], hi[5], hi[6], hi[7]);
                dl[0] = make_uint4(lo[0], lo[1], lo[2], lo[3]);
                dl[1] = make_uint4(lo[4], lo[5], lo[6], lo[7]);
            }
        }
        CP_WAIT0();
        __syncthreads();

        // ---- MMA mainloop: 4 k16-steps, 5 MMAs per tile-pair ----
        #pragma unroll
        for (int ks = 0; ks < 4; ks++) {
            const int kk = ks * 16;
            uint32_t a[3][4];
            #pragma unroll
            for (int mat = 0; mat < 3; mat++) {
                uint32_t addr = sA + mat * A_MAT_B
                              + (mrow0 + (lane & 15)) * (ASTR * 2)
                              + (kk + ((lane >> 4) * 8)) * 2;
                LDSM_X4(a[mat], addr);
            }
            #pragma unroll
            for (int np = 0; np < 4; np++) {
                const int ncol = ncol0 + np * 16;
                uint32_t b[4][4];
                #pragma unroll
                for (int mat = 0; mat < 4; mat++) {
                    int quad = lane >> 3;
                    uint32_t addr = sB + mat * B_MAT_B
                                  + (kk + (quad & 1) * 8 + (lane & 7)) * (BSTR * 2)
                                  + (ncol + (quad >> 1) * 8) * 2;
                    LDSM_X4T(b[mat], addr);
                }
                #pragma unroll
                for (int nt = 0; nt < 2; nt++) {
                    float* d = acc[np * 2 + nt];
                    mma16816(d, a[0], b[0] + nt * 2);   // m_hi * Wl_hi
                    mma16816(d, a[0], b[1] + nt * 2);   // m_hi * Wl_lo
                    mma16816(d, a[1], b[2] + nt * 2);   // x_hi * Wr_hi
                    mma16816(d, a[2], b[2] + nt * 2);   // x_lo * Wr_hi
                    mma16816(d, a[1], b[3] + nt * 2);   // x_hi * Wr_lo
                }
            }
        }
    }

    // ---- epilogue: out = x + relu(acc + b) ----
    const int rq = lane >> 2;
    const int cq = (lane & 3) * 2;
    #pragma unroll
    for (int h = 0; h < 2; h++) {
        int row = m0 + mrow0 + h * 8 + rq;
        if (row < N_NODES) {
            #pragma unroll
            for (int nt = 0; nt < 8; nt++) {
                int col = ncol0 + nt * 8 + cq;
                float d0 = acc[nt][h * 2 + 0];
                float d1 = acc[nt][h * 2 + 1];
                float2 bv = *reinterpret_cast<const float2*>(bl + col);
                float2 xv = *reinterpret_cast<const float2*>(x + (size_t)row * D + col);
                float2 o;
                o.x = xv.x + fmaxf(d0 + bv.x, 0.f);
                o.y = xv.y + fmaxf(d1 + bv.y, 0.f);
                *reinterpret_cast<float2*>(out + (size_t)row * D + col) = o;
            }
        }
    }
}

// ---------------------------------------------------------------------------
// launch
// ---------------------------------------------------------------------------
extern "C" void kernel_launch(void* const* d_in, const int* in_sizes, int n_in,
                              void* d_out, int out_size) {
    const float* x  = (const float*)d_in[0];
    const int*   ei = (const int*)d_in[1];
    const float* Wl = (const float*)d_in[2];
    const float* bl = (const float*)d_in[3];
    const float* Wr = (const float*)d_in[4];
    float* out = (float*)d_out;
    (void)in_sizes; (void)n_in; (void)out_size;

    // 1. fused weight prep + x->fp16 conversion
    conv_prep<<<PREP_BLOCKS + XCONV_BLOCKS, 256>>>(x, Wl, Wr);

    // 2. edge scatter: fp16 gather + fp16 v4 red (g_sumh zeroed by prev gemm)
    {
        int warps = (N_EDGES + 1) / 2;               // 312500
        int blocks = (warps * 32 + 255) / 256;       // 39063
        scatter_kernel<<<blocks, 256>>>(ei);
    }

    // 3. inverse degree (re-zeroes g_deg)
    inv_kernel<<<(N_NODES + 255) / 256, 256>>>();

    // 4. HMMA dual GEMM + bias + relu + residual (re-zeroes g_sumh)
    cudaFuncSetAttribute(gemm_mma, cudaFuncAttributeMaxDynamicSharedMemorySize,
                         SMEM_TOTAL);
    gemm_mma<<<(N_NODES + 63) / 64, 256, SMEM_TOTAL>>>(x, bl, out);
}

// round 14
// speedup vs baseline: 1.0688x; 1.0688x over previous
#include <cuda_runtime.h>
#include <cuda_fp16.h>
#include <cstdint>

#define N_NODES 50000
#define D 128
#define N_EDGES 625000
#define PREP_BLOCKS 128
#define XCONV_BLOCKS ((N_NODES * D / 8 + 255) / 256)   // 3125

// Device-global scratch (allocation-free rule; BSS zero-initialized)
__device__ __half g_xh[N_NODES * D];          // fp16 copy of x (scatter gather + gemm A)
__device__ __half g_sumh[N_NODES * D];        // fp16 edge-sum accumulator (re-zeroed by gemm)
__device__ float g_deg[N_NODES];              // re-zeroed by gemm each run
__device__ __half g_W[4 * 128 * 128];         // Wl_hi, Wl_lo, Wr_hi, Wr_lo (fp16 hi/lo) [mat][k][n]

// ---------------------------------------------------------------------------
// helpers
// ---------------------------------------------------------------------------
__device__ __forceinline__ uint32_t smem_u32(const void* p) {
    uint32_t a;
    asm("{ .reg .u64 t; cvta.to.shared.u64 t, %1; cvt.u32.u64 %0, t; }" : "=r"(a) : "l"(p));
    return a;
}

#define CP_ASYNC16(dst, src) \
    asm volatile("cp.async.cg.shared.global [%0], [%1], 16;" :: "r"(dst), "l"(src))
#define CP_ASYNC16Z(dst, src, sz) \
    asm volatile("cp.async.cg.shared.global [%0], [%1], 16, %2;" :: "r"(dst), "l"(src), "r"(sz))
#define CP_COMMIT() asm volatile("cp.async.commit_group;")
#define CP_WAIT0()  asm volatile("cp.async.wait_group 0;" ::: "memory")

#define LDSM_X4(r, addr) \
    asm volatile("ldmatrix.sync.aligned.m8n8.x4.shared.b16 {%0,%1,%2,%3}, [%4];" \
                 : "=r"((r)[0]), "=r"((r)[1]), "=r"((r)[2]), "=r"((r)[3]) : "r"(addr))
#define LDSM_X4T(r, addr) \
    asm volatile("ldmatrix.sync.aligned.m8n8.x4.trans.shared.b16 {%0,%1,%2,%3}, [%4];" \
                 : "=r"((r)[0]), "=r"((r)[1]), "=r"((r)[2]), "=r"((r)[3]) : "r"(addr))

__device__ __forceinline__ void mma16816h(float* d, const uint32_t* a, const uint32_t* b) {
    asm volatile(
        "mma.sync.aligned.m16n8k16.row.col.f32.f16.f16.f32 "
        "{%0,%1,%2,%3}, {%4,%5,%6,%7}, {%8,%9}, {%0,%1,%2,%3};"
        : "+f"(d[0]), "+f"(d[1]), "+f"(d[2]), "+f"(d[3])
        : "r"(a[0]), "r"(a[1]), "r"(a[2]), "r"(a[3]), "r"(b[0]), "r"(b[1]));
}

__device__ __forceinline__ uint32_t h2u(__half2 h) {
    uint32_t u;
    __builtin_memcpy(&u, &h, 4);
    return u;
}

// ---------------------------------------------------------------------------
// 1. fused: weight prep fp16 hi/lo (blocks 0..127) + x -> fp16 (rest)
// ---------------------------------------------------------------------------
__global__ void conv_prep(const float* __restrict__ x,
                          const float* __restrict__ Wl,
                          const float* __restrict__ Wr) {
    int tid = threadIdx.x;
    if (blockIdx.x < PREP_BLOCKS) {
        int idx = blockIdx.x * 256 + tid;        // 0..32767
        int m2 = idx >> 14;
        int k  = (idx >> 7) & 127;
        int n  = idx & 127;
        float w = (m2 ? Wr : Wl)[k * 128 + n];
        __half h = __float2half_rn(w);
        __half l = __float2half_rn(w - __half2float(h));
        g_W[(m2 * 2 + 0) * 16384 + k * 128 + n] = h;
        g_W[(m2 * 2 + 1) * 16384 + k * 128 + n] = l;
        return;
    }
    int i = ((int)blockIdx.x - PREP_BLOCKS) * 256 + tid;   // one 8-float chunk
    if (i >= N_NODES * D / 8) return;
    const float4* xs = reinterpret_cast<const float4*>(x) + i * 2;
    float4 a = xs[0], b = xs[1];
    uint4 o;
    o.x = h2u(__floats2half2_rn(a.x, a.y));
    o.y = h2u(__floats2half2_rn(a.z, a.w));
    o.z = h2u(__floats2half2_rn(b.x, b.y));
    o.w = h2u(__floats2half2_rn(b.z, b.w));
    reinterpret_cast<uint4*>(g_xh)[i] = o;
}

// ---------------------------------------------------------------------------
// 2. edge scatter: 16 lanes per edge (2 edges/warp). fp16 gather,
//    red.global.add.noftz.v4.f16x2 (LTS byte/op balanced).
// ---------------------------------------------------------------------------
__global__ void scatter_kernel(const int* __restrict__ ei) {
    int warp = (blockIdx.x * blockDim.x + threadIdx.x) >> 5;
    int lane = threadIdx.x & 31;
    int li = lane & 15;
    int e = warp * 2 + (lane >> 4);
    if (e >= N_EDGES) return;
    int src = ei[e];
    int dst = ei[N_EDGES + e];

    uint4 v = reinterpret_cast<const uint4*>(g_xh + (size_t)src * D)[li];
    __half* dptr = g_sumh + (size_t)dst * D + li * 8;
    asm volatile("red.global.add.noftz.v4.f16x2 [%0], {%1, %2, %3, %4};"
                 :: "l"(dptr), "r"(v.x), "r"(v.y), "r"(v.z), "r"(v.w)
                 : "memory");
    if (li == 0) atomicAdd(g_deg + dst, 1.0f);
}

// ---------------------------------------------------------------------------
// 3. fp16-HMMA GEMM: out = x + relu(mean@Wl + x@Wr + b)
//    4 MMAs/tile-step: m*(Wl_hi+Wl_lo) + x*(Wr_hi+Wr_lo), all fp16 operands.
//    A mats: 0 = mean (g_sumh*invd), 1 = x (cp.async from g_xh).
//    Computes invd from g_deg (re-zeroes it); re-zeroes g_sumh after read.
//    64x128 tile/CTA, 88KB smem -> 2 CTAs/SM.
// ---------------------------------------------------------------------------
#define ASTR 72
#define BSTR 136
#define A_MAT_B (64 * ASTR * 2)       // 9216 B
#define B_MAT_B (64 * BSTR * 2)       // 17408 B
#define SM_A_B (2 * A_MAT_B)          // 18432 B
#define SM_B_B (4 * B_MAT_B)          // 69632 B
#define SMEM_TOTAL (SM_A_B + SM_B_B)  // 88064 B -> 2 CTAs/SM

__global__ __launch_bounds__(256, 2)
void gemm_mma(const float* __restrict__ x,
              const float* __restrict__ bl,
              float* __restrict__ out) {
    extern __shared__ char sm[];
    const uint32_t sA = smem_u32(sm);
    const uint32_t sB = sA + SM_A_B;

    const int tid = threadIdx.x;
    const int lane = tid & 31;
    const int w = tid >> 5;
    const int m0 = blockIdx.x * 64;
    const int mrow0 = (w >> 1) * 16;
    const int ncol0 = (w & 1) * 64;

    // A-conversion map: 4 threads per row, 16 cols each
    const int cr = tid >> 2;
    const int cpart = tid & 3;
    const int crow = m0 + cr;
    const bool cvalid = crow < N_NODES;
    float invd = 1.0f;
    if (cvalid) {
        invd = 1.0f / fmaxf(g_deg[crow], 1.0f);
        if (cpart == 0) g_deg[crow] = 0.f;      // re-zero for next replay
    }

    float acc[8][4];
    #pragma unroll
    for (int nt = 0; nt < 8; nt++)
        #pragma unroll
        for (int q = 0; q < 4; q++) acc[nt][q] = 0.f;

    for (int c = 0; c < 2; c++) {
        const int k0 = c * 64;
        __syncthreads();    // previous chunk's MMAs done before smem overwrite

        // ---- B: 4 fp16 mats x 64k x 128n via cp.async ----
        #pragma unroll
        for (int i = 0; i < 16; i++) {
            int idx = tid + i * 256;          // 0..4095
            int mat = idx >> 10;
            int rem = idx & 1023;
            int r = rem >> 4, sg = rem & 15;
            uint32_t dst = sB + mat * B_MAT_B + r * (BSTR * 2) + sg * 16;
            const void* src = g_W + mat * 16384 + (k0 + r) * 128 + sg * 8;
            CP_ASYNC16(dst, src);
        }
        // ---- A mat 1 (x fp16) via cp.async from g_xh: 64 rows x 64 cols ----
        #pragma unroll
        for (int i = 0; i < 2; i++) {
            int idx = tid + i * 256;          // 0..511
            int r = idx >> 3, sg = idx & 7;
            int row = m0 + r;
            bool valid = row < N_NODES;
            uint32_t dst = sA + 1 * A_MAT_B + r * (ASTR * 2) + sg * 16;
            const void* src = valid ? (const void*)(g_xh + (size_t)row * D + k0 + sg * 8)
                                    : (const void*)g_xh;
            CP_ASYNC16Z(dst, src, valid ? 16 : 0);
        }
        CP_COMMIT();

        // ---- A mat 0 (mean fp16): g_sumh * invd; re-zero after read ----
        {
            uint4* hp = cvalid
                ? reinterpret_cast<uint4*>(g_sumh + (size_t)crow * D + k0 + cpart * 16)
                : nullptr;
            uint4 u0 = cvalid ? hp[0] : make_uint4(0, 0, 0, 0);
            uint4 u1 = cvalid ? hp[1] : make_uint4(0, 0, 0, 0);
            uint32_t h2s[8] = {u0.x, u0.y, u0.z, u0.w, u1.x, u1.y, u1.z, u1.w};
            uint32_t mo[8];
            #pragma unroll
            for (int i = 0; i < 8; i++) {
                float2 f = __half22float2(*reinterpret_cast<__half2*>(&h2s[i]));
                mo[i] = h2u(__floats2half2_rn(f.x * invd, f.y * invd));
            }
            uint4* dm = reinterpret_cast<uint4*>(sm + 0 * A_MAT_B + cr * (ASTR * 2) + cpart * 32);
            dm[0] = make_uint4(mo[0], mo[1], mo[2], mo[3]);
            dm[1] = make_uint4(mo[4], mo[5], mo[6], mo[7]);
            if (cvalid) {
                hp[0] = make_uint4(0, 0, 0, 0);   // re-zero fp16 sums for next replay
                hp[1] = make_uint4(0, 0, 0, 0);
            }
        }
        CP_WAIT0();
        __syncthreads();

        // ---- MMA mainloop: 4 k16-steps, 4 fp16 MMAs per tile-pair ----
        #pragma unroll
        for (int ks = 0; ks < 4; ks++) {
            const int kk = ks * 16;
            uint32_t a[2][4];
            #pragma unroll
            for (int mat = 0; mat < 2; mat++) {
                uint32_t addr = sA + mat * A_MAT_B
                              + (mrow0 + (lane & 15)) * (ASTR * 2)
                              + (kk + ((lane >> 4) * 8)) * 2;
                LDSM_X4(a[mat], addr);
            }
            #pragma unroll
            for (int np = 0; np < 4; np++) {
                const int ncol = ncol0 + np * 16;
                uint32_t b[4][4];
                #pragma unroll
                for (int mat = 0; mat < 4; mat++) {
                    int quad = lane >> 3;
                    uint32_t addr = sB + mat * B_MAT_B
                                  + (kk + (quad & 1) * 8 + (lane & 7)) * (BSTR * 2)
                                  + (ncol + (quad >> 1) * 8) * 2;
                    LDSM_X4T(b[mat], addr);
                }
                #pragma unroll
                for (int nt = 0; nt < 2; nt++) {
                    float* d = acc[np * 2 + nt];
                    mma16816h(d, a[0], b[0] + nt * 2);   // m * Wl_hi
                    mma16816h(d, a[0], b[1] + nt * 2);   // m * Wl_lo
                    mma16816h(d, a[1], b[2] + nt * 2);   // x * Wr_hi
                    mma16816h(d, a[1], b[3] + nt * 2);   // x * Wr_lo
                }
            }
        }
    }

    // ---- epilogue: out = x + relu(acc + b) ----
    const int rq = lane >> 2;
    const int cq = (lane & 3) * 2;
    #pragma unroll
    for (int h = 0; h < 2; h++) {
        int row = m0 + mrow0 + h * 8 + rq;
        if (row < N_NODES) {
            #pragma unroll
            for (int nt = 0; nt < 8; nt++) {
                int col = ncol0 + nt * 8 + cq;
                float d0 = acc[nt][h * 2 + 0];
                float d1 = acc[nt][h * 2 + 1];
                float2 bv = *reinterpret_cast<const float2*>(bl + col);
                float2 xv = *reinterpret_cast<const float2*>(x + (size_t)row * D + col);
                float2 o;
                o.x = xv.x + fmaxf(d0 + bv.x, 0.f);
                o.y = xv.y + fmaxf(d1 + bv.y, 0.f);
                *reinterpret_cast<float2*>(out + (size_t)row * D + col) = o;
            }
        }
    }
}

// ---------------------------------------------------------------------------
// launch
// ---------------------------------------------------------------------------
extern "C" void kernel_launch(void* const* d_in, const int* in_sizes, int n_in,
                              void* d_out, int out_size) {
    const float* x  = (const float*)d_in[0];
    const int*   ei = (const int*)d_in[1];
    const float* Wl = (const float*)d_in[2];
    const float* bl = (const float*)d_in[3];
    const float* Wr = (const float*)d_in[4];
    float* out = (float*)d_out;
    (void)in_sizes; (void)n_in; (void)out_size;

    // 1. fused weight prep (fp16 hi/lo) + x->fp16 conversion
    conv_prep<<<PREP_BLOCKS + XCONV_BLOCKS, 256>>>(x, Wl, Wr);

    // 2. edge scatter: fp16 gather + fp16 v4 red (g_sumh zeroed by prev gemm)
    {
        int warps = (N_EDGES + 1) / 2;               // 312500
        int blocks = (warps * 32 + 255) / 256;       // 39063
        scatter_kernel<<<blocks, 256>>>(ei);
    }

    // 3. fp16-HMMA dual GEMM + bias + relu + residual
    //    (computes invd, re-zeroes g_deg and g_sumh)
    cudaFuncSetAttribute(gemm_mma, cudaFuncAttributeMaxDynamicSharedMemorySize,
                         SMEM_TOTAL);
    gemm_mma<<<(N_NODES + 63) / 64, 256, SMEM_TOTAL>>>(x, bl, out);
}

// round 15
// speedup vs baseline: 1.2200x; 1.1415x over previous
#include <cuda_runtime.h>
#include <cuda_fp16.h>
#include <cstdint>

#define N_NODES 50000
#define D 128
#define N_EDGES 625000
#define PREP_BLOCKS 128
#define XCONV_BLOCKS ((N_NODES * D / 8 + 255) / 256)   // 3125

// Device-global scratch (allocation-free rule; BSS zero-initialized)
__device__ __half g_xh[N_NODES * D];          // fp16 copy of x (scatter gather + gemm A)
__device__ __half g_sumh[N_NODES * D];        // fp16 edge-sum accumulator (re-zeroed by gemm)
__device__ float g_deg[N_NODES];              // re-zeroed by gemm each run
__device__ __half g_W[2 * 128 * 128];         // Wl, Wr (fp16) [mat][k][n]

// ---------------------------------------------------------------------------
// helpers
// ---------------------------------------------------------------------------
__device__ __forceinline__ uint32_t smem_u32(const void* p) {
    uint32_t a;
    asm("{ .reg .u64 t; cvta.to.shared.u64 t, %1; cvt.u32.u64 %0, t; }" : "=r"(a) : "l"(p));
    return a;
}

#define CP_ASYNC16(dst, src) \
    asm volatile("cp.async.cg.shared.global [%0], [%1], 16;" :: "r"(dst), "l"(src))
#define CP_ASYNC16Z(dst, src, sz) \
    asm volatile("cp.async.cg.shared.global [%0], [%1], 16, %2;" :: "r"(dst), "l"(src), "r"(sz))
#define CP_COMMIT() asm volatile("cp.async.commit_group;")
#define CP_WAIT0()  asm volatile("cp.async.wait_group 0;" ::: "memory")

#define LDSM_X4(r, addr) \
    asm volatile("ldmatrix.sync.aligned.m8n8.x4.shared.b16 {%0,%1,%2,%3}, [%4];" \
                 : "=r"((r)[0]), "=r"((r)[1]), "=r"((r)[2]), "=r"((r)[3]) : "r"(addr))
#define LDSM_X4T(r, addr) \
    asm volatile("ldmatrix.sync.aligned.m8n8.x4.trans.shared.b16 {%0,%1,%2,%3}, [%4];" \
                 : "=r"((r)[0]), "=r"((r)[1]), "=r"((r)[2]), "=r"((r)[3]) : "r"(addr))

__device__ __forceinline__ void mma16816h(float* d, const uint32_t* a, const uint32_t* b) {
    asm volatile(
        "mma.sync.aligned.m16n8k16.row.col.f32.f16.f16.f32 "
        "{%0,%1,%2,%3}, {%4,%5,%6,%7}, {%8,%9}, {%0,%1,%2,%3};"
        : "+f"(d[0]), "+f"(d[1]), "+f"(d[2]), "+f"(d[3])
        : "r"(a[0]), "r"(a[1]), "r"(a[2]), "r"(a[3]), "r"(b[0]), "r"(b[1]));
}

__device__ __forceinline__ uint32_t h2u(__half2 h) {
    uint32_t u;
    __builtin_memcpy(&u, &h, 4);
    return u;
}

// ---------------------------------------------------------------------------
// 1. fused: weight prep fp16 (blocks 0..127) + x -> fp16 (rest)
// ---------------------------------------------------------------------------
__global__ void conv_prep(const float* __restrict__ x,
                          const float* __restrict__ Wl,
                          const float* __restrict__ Wr) {
    int tid = threadIdx.x;
    if (blockIdx.x < PREP_BLOCKS) {
        int idx = blockIdx.x * 256 + tid;        // 0..32767
        int m2 = idx >> 14;
        int rem = idx & 16383;
        float w = (m2 ? Wr : Wl)[rem];
        g_W[m2 * 16384 + rem] = __float2half_rn(w);
        return;
    }
    int i = ((int)blockIdx.x - PREP_BLOCKS) * 256 + tid;   // one 8-float chunk
    if (i >= N_NODES * D / 8) return;
    const float4* xs = reinterpret_cast<const float4*>(x) + i * 2;
    float4 a = xs[0], b = xs[1];
    uint4 o;
    o.x = h2u(__floats2half2_rn(a.x, a.y));
    o.y = h2u(__floats2half2_rn(a.z, a.w));
    o.z = h2u(__floats2half2_rn(b.x, b.y));
    o.w = h2u(__floats2half2_rn(b.z, b.w));
    reinterpret_cast<uint4*>(g_xh)[i] = o;
}

// ---------------------------------------------------------------------------
// 2. edge scatter: 16 lanes per edge (2 edges/warp). fp16 gather,
//    red.global.add.noftz.v4.f16x2 (LTS byte/op balanced).
// ---------------------------------------------------------------------------
__global__ void scatter_kernel(const int* __restrict__ ei) {
    int warp = (blockIdx.x * blockDim.x + threadIdx.x) >> 5;
    int lane = threadIdx.x & 31;
    int li = lane & 15;
    int e = warp * 2 + (lane >> 4);
    if (e >= N_EDGES) return;
    int src = ei[e];
    int dst = ei[N_EDGES + e];

    uint4 v = reinterpret_cast<const uint4*>(g_xh + (size_t)src * D)[li];
    __half* dptr = g_sumh + (size_t)dst * D + li * 8;
    asm volatile("red.global.add.noftz.v4.f16x2 [%0], {%1, %2, %3, %4};"
                 :: "l"(dptr), "r"(v.x), "r"(v.y), "r"(v.z), "r"(v.w)
                 : "memory");
    if (li == 0) atomicAdd(g_deg + dst, 1.0f);
}

// ---------------------------------------------------------------------------
// 3. fp16-HMMA GEMM: out = x + relu(mean@Wl + x@Wr + b)
//    2 MMAs/tile-step: m*Wl + x*Wr, pure fp16 operands, fp32 accum.
//    A mats: 0 = mean (g_sumh*invd), 1 = x (cp.async from g_xh).
//    Computes invd from g_deg (re-zeroes it); re-zeroes g_sumh after read.
//    64x128 tile/CTA, 53KB smem -> 3 CTAs/SM.
// ---------------------------------------------------------------------------
#define ASTR 72
#define BSTR 136
#define A_MAT_B (64 * ASTR * 2)       // 9216 B
#define B_MAT_B (64 * BSTR * 2)       // 17408 B
#define SM_A_B (2 * A_MAT_B)          // 18432 B
#define SM_B_B (2 * B_MAT_B)          // 34816 B
#define SMEM_TOTAL (SM_A_B + SM_B_B)  // 53248 B -> 3 CTAs/SM

__global__ __launch_bounds__(256, 3)
void gemm_mma(const float* __restrict__ x,
              const float* __restrict__ bl,
              float* __restrict__ out) {
    extern __shared__ char sm[];
    const uint32_t sA = smem_u32(sm);
    const uint32_t sB = sA + SM_A_B;

    const int tid = threadIdx.x;
    const int lane = tid & 31;
    const int w = tid >> 5;
    const int m0 = blockIdx.x * 64;
    const int mrow0 = (w >> 1) * 16;
    const int ncol0 = (w & 1) * 64;

    // A-conversion map: 4 threads per row, 16 cols each
    const int cr = tid >> 2;
    const int cpart = tid & 3;
    const int crow = m0 + cr;
    const bool cvalid = crow < N_NODES;
    float invd = 1.0f;
    if (cvalid) {
        invd = 1.0f / fmaxf(g_deg[crow], 1.0f);
        if (cpart == 0) g_deg[crow] = 0.f;      // re-zero for next replay
    }

    float acc[8][4];
    #pragma unroll
    for (int nt = 0; nt < 8; nt++)
        #pragma unroll
        for (int q = 0; q < 4; q++) acc[nt][q] = 0.f;

    for (int c = 0; c < 2; c++) {
        const int k0 = c * 64;
        __syncthreads();    // previous chunk's MMAs done before smem overwrite

        // ---- B: 2 fp16 mats x 64k x 128n via cp.async ----
        #pragma unroll
        for (int i = 0; i < 8; i++) {
            int idx = tid + i * 256;          // 0..2047
            int mat = idx >> 10;
            int rem = idx & 1023;
            int r = rem >> 4, sg = rem & 15;
            uint32_t dst = sB + mat * B_MAT_B + r * (BSTR * 2) + sg * 16;
            const void* src = g_W + mat * 16384 + (k0 + r) * 128 + sg * 8;
            CP_ASYNC16(dst, src);
        }
        // ---- A mat 1 (x fp16) via cp.async from g_xh: 64 rows x 64 cols ----
        #pragma unroll
        for (int i = 0; i < 2; i++) {
            int idx = tid + i * 256;          // 0..511
            int r = idx >> 3, sg = idx & 7;
            int row = m0 + r;
            bool valid = row < N_NODES;
            uint32_t dst = sA + 1 * A_MAT_B + r * (ASTR * 2) + sg * 16;
            const void* src = valid ? (const void*)(g_xh + (size_t)row * D + k0 + sg * 8)
                                    : (const void*)g_xh;
            CP_ASYNC16Z(dst, src, valid ? 16 : 0);
        }
        CP_COMMIT();

        // ---- A mat 0 (mean fp16): g_sumh * invd; re-zero after read ----
        {
            uint4* hp = cvalid
                ? reinterpret_cast<uint4*>(g_sumh + (size_t)crow * D + k0 + cpart * 16)
                : nullptr;
            uint4 u0 = cvalid ? hp[0] : make_uint4(0, 0, 0, 0);
            uint4 u1 = cvalid ? hp[1] : make_uint4(0, 0, 0, 0);
            uint32_t h2s[8] = {u0.x, u0.y, u0.z, u0.w, u1.x, u1.y, u1.z, u1.w};
            uint32_t mo[8];
            #pragma unroll
            for (int i = 0; i < 8; i++) {
                float2 f = __half22float2(*reinterpret_cast<__half2*>(&h2s[i]));
                mo[i] = h2u(__floats2half2_rn(f.x * invd, f.y * invd));
            }
            uint4* dm = reinterpret_cast<uint4*>(sm + 0 * A_MAT_B + cr * (ASTR * 2) + cpart * 32);
            dm[0] = make_uint4(mo[0], mo[1], mo[2], mo[3]);
            dm[1] = make_uint4(mo[4], mo[5], mo[6], mo[7]);
            if (cvalid) {
                hp[0] = make_uint4(0, 0, 0, 0);   // re-zero fp16 sums for next replay
                hp[1] = make_uint4(0, 0, 0, 0);
            }
        }
        CP_WAIT0();
        __syncthreads();

        // ---- MMA mainloop: 4 k16-steps, 2 fp16 MMAs per tile-pair ----
        #pragma unroll
        for (int ks = 0; ks < 4; ks++) {
            const int kk = ks * 16;
            uint32_t a[2][4];
            #pragma unroll
            for (int mat = 0; mat < 2; mat++) {
                uint32_t addr = sA + mat * A_MAT_B
                              + (mrow0 + (lane & 15)) * (ASTR * 2)
                              + (kk + ((lane >> 4) * 8)) * 2;
                LDSM_X4(a[mat], addr);
            }
            #pragma unroll
            for (int np = 0; np < 4; np++) {
                const int ncol = ncol0 + np * 16;
                uint32_t b[2][4];
                #pragma unroll
                for (int mat = 0; mat < 2; mat++) {
                    int quad = lane >> 3;
                    uint32_t addr = sB + mat * B_MAT_B
                                  + (kk + (quad & 1) * 8 + (lane & 7)) * (BSTR * 2)
                                  + (ncol + (quad >> 1) * 8) * 2;
                    LDSM_X4T(b[mat], addr);
                }
                #pragma unroll
                for (int nt = 0; nt < 2; nt++) {
                    float* d = acc[np * 2 + nt];
                    mma16816h(d, a[0], b[0] + nt * 2);   // m * Wl
                    mma16816h(d, a[1], b[1] + nt * 2);   // x * Wr
                }
            }
        }
    }

    // ---- epilogue: out = x + relu(acc + b) ----
    const int rq = lane >> 2;
    const int cq = (lane & 3) * 2;
    #pragma unroll
    for (int h = 0; h < 2; h++) {
        int row = m0 + mrow0 + h * 8 + rq;
        if (row < N_NODES) {
            #pragma unroll
            for (int nt = 0; nt < 8; nt++) {
                int col = ncol0 + nt * 8 + cq;
                float d0 = acc[nt][h * 2 + 0];
                float d1 = acc[nt][h * 2 + 1];
                float2 bv = *reinterpret_cast<const float2*>(bl + col);
                float2 xv = *reinterpret_cast<const float2*>(x + (size_t)row * D + col);
                float2 o;
                o.x = xv.x + fmaxf(d0 + bv.x, 0.f);
                o.y = xv.y + fmaxf(d1 + bv.y, 0.f);
                *reinterpret_cast<float2*>(out + (size_t)row * D + col) = o;
            }
        }
    }
}

// ---------------------------------------------------------------------------
// launch
// ---------------------------------------------------------------------------
extern "C" void kernel_launch(void* const* d_in, const int* in_sizes, int n_in,
                              void* d_out, int out_size) {
    const float* x  = (const float*)d_in[0];
    const int*   ei = (const int*)d_in[1];
    const float* Wl = (const float*)d_in[2];
    const float* bl = (const float*)d_in[3];
    const float* Wr = (const float*)d_in[4];
    float* out = (float*)d_out;
    (void)in_sizes; (void)n_in; (void)out_size;

    // 1. fused weight prep (fp16) + x->fp16 conversion
    conv_prep<<<PREP_BLOCKS + XCONV_BLOCKS, 256>>>(x, Wl, Wr);

    // 2. edge scatter: fp16 gather + fp16 v4 red (g_sumh zeroed by prev gemm)
    {
        int warps = (N_EDGES + 1) / 2;               // 312500
        int blocks = (warps * 32 + 255) / 256;       // 39063
        scatter_kernel<<<blocks, 256>>>(ei);
    }

    // 3. fp16-HMMA dual GEMM + bias + relu + residual
    //    (computes invd, re-zeroes g_deg and g_sumh)
    cudaFuncSetAttribute(gemm_mma, cudaFuncAttributeMaxDynamicSharedMemorySize,
                         SMEM_TOTAL);
    gemm_mma<<<(N_NODES + 63) / 64, 256, SMEM_TOTAL>>>(x, bl, out);
}

// round 16
// speedup vs baseline: 1.2434x; 1.0192x over previous
#include <cuda_runtime.h>
#include <cuda_fp16.h>
#include <cstdint>

#define N_NODES 50000
#define D 128
#define N_EDGES 625000
#define PREP_BLOCKS 128
#define XCHUNKS (N_NODES * D / 8)                      // 800000 16B-chunks
#define XCONV_BLOCKS ((XCHUNKS + 1023) / 1024)         // 782 (4 chunks/thread)

// Device-global scratch (allocation-free rule; BSS zero-initialized)
__device__ __half g_xh[N_NODES * D];          // fp16 copy of x (scatter gather + gemm A)
__device__ __half g_sumh[N_NODES * D];        // fp16 edge-sum accumulator (re-zeroed by gemm)
__device__ float g_deg[N_NODES];              // re-zeroed by gemm each run
__device__ __half g_W[2 * 128 * 128];         // Wl, Wr (fp16) [mat][k][n]

// ---------------------------------------------------------------------------
// helpers
// ---------------------------------------------------------------------------
__device__ __forceinline__ uint32_t smem_u32(const void* p) {
    uint32_t a;
    asm("{ .reg .u64 t; cvta.to.shared.u64 t, %1; cvt.u32.u64 %0, t; }" : "=r"(a) : "l"(p));
    return a;
}

#define CP_ASYNC16(dst, src) \
    asm volatile("cp.async.cg.shared.global [%0], [%1], 16;" :: "r"(dst), "l"(src))
#define CP_ASYNC16Z(dst, src, sz) \
    asm volatile("cp.async.cg.shared.global [%0], [%1], 16, %2;" :: "r"(dst), "l"(src), "r"(sz))
#define CP_COMMIT() asm volatile("cp.async.commit_group;")
#define CP_WAIT0()  asm volatile("cp.async.wait_group 0;" ::: "memory")

#define LDSM_X4(r, addr) \
    asm volatile("ldmatrix.sync.aligned.m8n8.x4.shared.b16 {%0,%1,%2,%3}, [%4];" \
                 : "=r"((r)[0]), "=r"((r)[1]), "=r"((r)[2]), "=r"((r)[3]) : "r"(addr))
#define LDSM_X4T(r, addr) \
    asm volatile("ldmatrix.sync.aligned.m8n8.x4.trans.shared.b16 {%0,%1,%2,%3}, [%4];" \
                 : "=r"((r)[0]), "=r"((r)[1]), "=r"((r)[2]), "=r"((r)[3]) : "r"(addr))

__device__ __forceinline__ void mma16816h(float* d, const uint32_t* a, const uint32_t* b) {
    asm volatile(
        "mma.sync.aligned.m16n8k16.row.col.f32.f16.f16.f32 "
        "{%0,%1,%2,%3}, {%4,%5,%6,%7}, {%8,%9}, {%0,%1,%2,%3};"
        : "+f"(d[0]), "+f"(d[1]), "+f"(d[2]), "+f"(d[3])
        : "r"(a[0]), "r"(a[1]), "r"(a[2]), "r"(a[3]), "r"(b[0]), "r"(b[1]));
}

__device__ __forceinline__ uint32_t h2u(__half2 h) {
    uint32_t u;
    __builtin_memcpy(&u, &h, 4);
    return u;
}

// ---------------------------------------------------------------------------
// 1. fused: weight prep fp16 (blocks 0..127) + x -> fp16 (rest).
//    x conversion: 4 chunks/thread, loads front-batched for MLP ~8.
// ---------------------------------------------------------------------------
__global__ __launch_bounds__(256)
void conv_prep(const float* __restrict__ x,
               const float* __restrict__ Wl,
               const float* __restrict__ Wr) {
    int tid = threadIdx.x;
    if (blockIdx.x < PREP_BLOCKS) {
        int idx = blockIdx.x * 256 + tid;        // 0..32767
        int m2 = idx >> 14;
        int rem = idx & 16383;
        float w = (m2 ? Wr : Wl)[rem];
        g_W[m2 * 16384 + rem] = __float2half_rn(w);
        return;
    }
    int base = ((int)blockIdx.x - PREP_BLOCKS) * 1024 + tid;
    const float4* xs = reinterpret_cast<const float4*>(x);

    float4 a[4], b[4];
    bool v[4];
    #pragma unroll
    for (int j = 0; j < 4; j++) {
        int i = base + j * 256;
        v[j] = i < XCHUNKS;
        if (v[j]) {
            a[j] = xs[2 * i];
            b[j] = xs[2 * i + 1];
        }
    }
    #pragma unroll
    for (int j = 0; j < 4; j++) {
        if (v[j]) {
            uint4 o;
            o.x = h2u(__floats2half2_rn(a[j].x, a[j].y));
            o.y = h2u(__floats2half2_rn(a[j].z, a[j].w));
            o.z = h2u(__floats2half2_rn(b[j].x, b[j].y));
            o.w = h2u(__floats2half2_rn(b[j].z, b[j].w));
            reinterpret_cast<uint4*>(g_xh)[base + j * 256] = o;
        }
    }
}

// ---------------------------------------------------------------------------
// 2. edge scatter: 16 lanes per edge (2 edges/warp). fp16 gather,
//    red.global.add.noftz.v4.f16x2 (LTS byte/op balanced).
// ---------------------------------------------------------------------------
__global__ void scatter_kernel(const int* __restrict__ ei) {
    int warp = (blockIdx.x * blockDim.x + threadIdx.x) >> 5;
    int lane = threadIdx.x & 31;
    int li = lane & 15;
    int e = warp * 2 + (lane >> 4);
    if (e >= N_EDGES) return;
    int src = ei[e];
    int dst = ei[N_EDGES + e];

    uint4 v = reinterpret_cast<const uint4*>(g_xh + (size_t)src * D)[li];
    __half* dptr = g_sumh + (size_t)dst * D + li * 8;
    asm volatile("red.global.add.noftz.v4.f16x2 [%0], {%1, %2, %3, %4};"
                 :: "l"(dptr), "r"(v.x), "r"(v.y), "r"(v.z), "r"(v.w)
                 : "memory");
    if (li == 0) atomicAdd(g_deg + dst, 1.0f);
}

// ---------------------------------------------------------------------------
// 3. fp16-HMMA GEMM: out = x + relu(mean@Wl + x@Wr + b)
//    2 MMAs/tile-step: m*Wl + x*Wr, fp16 operands, fp32 accum.
//    A mats: 0 = mean (g_sumh*invd), 1 = x (cp.async from g_xh).
//    Computes invd from g_deg (re-zeroes it); re-zeroes g_sumh after read.
//    64x128 tile/CTA, 53KB smem -> 3 CTAs/SM.
// ---------------------------------------------------------------------------
#define ASTR 72
#define BSTR 136
#define A_MAT_B (64 * ASTR * 2)       // 9216 B
#define B_MAT_B (64 * BSTR * 2)       // 17408 B
#define SM_A_B (2 * A_MAT_B)          // 18432 B
#define SM_B_B (2 * B_MAT_B)          // 34816 B
#define SMEM_TOTAL (SM_A_B + SM_B_B)  // 53248 B -> 3 CTAs/SM

__global__ __launch_bounds__(256, 3)
void gemm_mma(const float* __restrict__ x,
              const float* __restrict__ bl,
              float* __restrict__ out) {
    extern __shared__ char sm[];
    const uint32_t sA = smem_u32(sm);
    const uint32_t sB = sA + SM_A_B;

    const int tid = threadIdx.x;
    const int lane = tid & 31;
    const int w = tid >> 5;
    const int m0 = blockIdx.x * 64;
    const int mrow0 = (w >> 1) * 16;
    const int ncol0 = (w & 1) * 64;

    // A-conversion map: 4 threads per row, 16 cols each
    const int cr = tid >> 2;
    const int cpart = tid & 3;
    const int crow = m0 + cr;
    const bool cvalid = crow < N_NODES;
    float invd = 1.0f;
    if (cvalid) {
        invd = 1.0f / fmaxf(g_deg[crow], 1.0f);
        if (cpart == 0) g_deg[crow] = 0.f;      // re-zero for next replay
    }

    float acc[8][4];
    #pragma unroll
    for (int nt = 0; nt < 8; nt++)
        #pragma unroll
        for (int q = 0; q < 4; q++) acc[nt][q] = 0.f;

    for (int c = 0; c < 2; c++) {
        const int k0 = c * 64;
        __syncthreads();    // previous chunk's MMAs done before smem overwrite

        // ---- B: 2 fp16 mats x 64k x 128n via cp.async ----
        #pragma unroll
        for (int i = 0; i < 8; i++) {
            int idx = tid + i * 256;          // 0..2047
            int mat = idx >> 10;
            int rem = idx & 1023;
            int r = rem >> 4, sg = rem & 15;
            uint32_t dst = sB + mat * B_MAT_B + r * (BSTR * 2) + sg * 16;
            const void* src = g_W + mat * 16384 + (k0 + r) * 128 + sg * 8;
            CP_ASYNC16(dst, src);
        }
        // ---- A mat 1 (x fp16) via cp.async from g_xh: 64 rows x 64 cols ----
        #pragma unroll
        for (int i = 0; i < 2; i++) {
            int idx = tid + i * 256;          // 0..511
            int r = idx >> 3, sg = idx & 7;
            int row = m0 + r;
            bool valid = row < N_NODES;
            uint32_t dst = sA + 1 * A_MAT_B + r * (ASTR * 2) + sg * 16;
            const void* src = valid ? (const void*)(g_xh + (size_t)row * D + k0 + sg * 8)
                                    : (const void*)g_xh;
            CP_ASYNC16Z(dst, src, valid ? 16 : 0);
        }
        CP_COMMIT();

        // ---- A mat 0 (mean fp16): g_sumh * invd; re-zero after read ----
        {
            uint4* hp = cvalid
                ? reinterpret_cast<uint4*>(g_sumh + (size_t)crow * D + k0 + cpart * 16)
                : nullptr;
            uint4 u0 = cvalid ? hp[0] : make_uint4(0, 0, 0, 0);
            uint4 u1 = cvalid ? hp[1] : make_uint4(0, 0, 0, 0);
            uint32_t h2s[8] = {u0.x, u0.y, u0.z, u0.w, u1.x, u1.y, u1.z, u1.w};
            uint32_t mo[8];
            #pragma unroll
            for (int i = 0; i < 8; i++) {
                float2 f = __half22float2(*reinterpret_cast<__half2*>(&h2s[i]));
                mo[i] = h2u(__floats2half2_rn(f.x * invd, f.y * invd));
            }
            uint4* dm = reinterpret_cast<uint4*>(sm + 0 * A_MAT_B + cr * (ASTR * 2) + cpart * 32);
            dm[0] = make_uint4(mo[0], mo[1], mo[2], mo[3]);
            dm[1] = make_uint4(mo[4], mo[5], mo[6], mo[7]);
            if (cvalid) {
                hp[0] = make_uint4(0, 0, 0, 0);   // re-zero fp16 sums for next replay
                hp[1] = make_uint4(0, 0, 0, 0);
            }
        }
        CP_WAIT0();
        __syncthreads();

        // ---- MMA mainloop: 4 k16-steps, 2 fp16 MMAs per tile-pair ----
        #pragma unroll
        for (int ks = 0; ks < 4; ks++) {
            const int kk = ks * 16;
            uint32_t a[2][4];
            #pragma unroll
            for (int mat = 0; mat < 2; mat++) {
                uint32_t addr = sA + mat * A_MAT_B
                              + (mrow0 + (lane & 15)) * (ASTR * 2)
                              + (kk + ((lane >> 4) * 8)) * 2;
                LDSM_X4(a[mat], addr);
            }
            #pragma unroll
            for (int np = 0; np < 4; np++) {
                const int ncol = ncol0 + np * 16;
                uint32_t b[2][4];
                #pragma unroll
                for (int mat = 0; mat < 2; mat++) {
                    int quad = lane >> 3;
                    uint32_t addr = sB + mat * B_MAT_B
                                  + (kk + (quad & 1) * 8 + (lane & 7)) * (BSTR * 2)
                                  + (ncol + (quad >> 1) * 8) * 2;
                    LDSM_X4T(b[mat], addr);
                }
                #pragma unroll
                for (int nt = 0; nt < 2; nt++) {
                    float* d = acc[np * 2 + nt];
                    mma16816h(d, a[0], b[0] + nt * 2);   // m * Wl
                    mma16816h(d, a[1], b[1] + nt * 2);   // x * Wr
                }
            }
        }
    }

    // ---- epilogue: out = x + relu(acc + b) ----
    const int rq = lane >> 2;
    const int cq = (lane & 3) * 2;
    #pragma unroll
    for (int h = 0; h < 2; h++) {
        int row = m0 + mrow0 + h * 8 + rq;
        if (row < N_NODES) {
            #pragma unroll
            for (int nt = 0; nt < 8; nt++) {
                int col = ncol0 + nt * 8 + cq;
                float d0 = acc[nt][h * 2 + 0];
                float d1 = acc[nt][h * 2 + 1];
                float2 bv = *reinterpret_cast<const float2*>(bl + col);
                float2 xv = *reinterpret_cast<const float2*>(x + (size_t)row * D + col);
                float2 o;
                o.x = xv.x + fmaxf(d0 + bv.x, 0.f);
                o.y = xv.y + fmaxf(d1 + bv.y, 0.f);
                *reinterpret_cast<float2*>(out + (size_t)row * D + col) = o;
            }
        }
    }
}

// ---------------------------------------------------------------------------
// launch
// ---------------------------------------------------------------------------
extern "C" void kernel_launch(void* const* d_in, const int* in_sizes, int n_in,
                              void* d_out, int out_size) {
    const float* x  = (const float*)d_in[0];
    const int*   ei = (const int*)d_in[1];
    const float* Wl = (const float*)d_in[2];
    const float* bl = (const float*)d_in[3];
    const float* Wr = (const float*)d_in[4];
    float* out = (float*)d_out;
    (void)in_sizes; (void)n_in; (void)out_size;

    // 1. fused weight prep (fp16) + x->fp16 conversion (MLP-batched)
    conv_prep<<<PREP_BLOCKS + XCONV_BLOCKS, 256>>>(x, Wl, Wr);

    // 2. edge scatter: fp16 gather + fp16 v4 red (g_sumh zeroed by prev gemm)
    {
        int warps = (N_EDGES + 1) / 2;               // 312500
        int blocks = (warps * 32 + 255) / 256;       // 39063
        scatter_kernel<<<blocks, 256>>>(ei);
    }

    // 3. fp16-HMMA dual GEMM + bias + relu + residual
    //    (computes invd, re-zeroes g_deg and g_sumh)
    cudaFuncSetAttribute(gemm_mma, cudaFuncAttributeMaxDynamicSharedMemorySize,
                         SMEM_TOTAL);
    gemm_mma<<<(N_NODES + 63) / 64, 256, SMEM_TOTAL>>>(x, bl, out);
}

// round 17
// speedup vs baseline: 1.3287x; 1.0685x over previous
#include <cuda_runtime.h>
#include <cuda_fp16.h>
#include <cstdint>

#define N_NODES 50000
#define D 128
#define N_EDGES 625000
#define PREP_BLOCKS 128
#define XCONV_BLOCKS ((N_NODES * D / 8 + 255) / 256)   // 3125

// Device-global scratch (allocation-free rule; BSS zero-initialized)
__device__ __half g_xh[N_NODES * D];          // fp16 copy of x (scatter gather + gemm A)
__device__ __half g_sumh[N_NODES * D];        // fp16 edge-sum accumulator (re-zeroed by gemm)
__device__ float g_deg[N_NODES];              // re-zeroed by gemm each run
__device__ __half g_W[2 * 128 * 128];         // Wl, Wr (fp16) [mat][k][n]

// ---------------------------------------------------------------------------
// helpers
// ---------------------------------------------------------------------------
__device__ __forceinline__ uint32_t smem_u32(const void* p) {
    uint32_t a;
    asm("{ .reg .u64 t; cvta.to.shared.u64 t, %1; cvt.u32.u64 %0, t; }" : "=r"(a) : "l"(p));
    return a;
}

#define CP_ASYNC16CA(dst, src) \
    asm volatile("cp.async.ca.shared.global [%0], [%1], 16;" :: "r"(dst), "l"(src))
#define CP_ASYNC16Z(dst, src, sz) \
    asm volatile("cp.async.cg.shared.global [%0], [%1], 16, %2;" :: "r"(dst), "l"(src), "r"(sz))
#define CP_COMMIT() asm volatile("cp.async.commit_group;")
#define CP_WAIT0()  asm volatile("cp.async.wait_group 0;" ::: "memory")

#define LDSM_X4(r, addr) \
    asm volatile("ldmatrix.sync.aligned.m8n8.x4.shared.b16 {%0,%1,%2,%3}, [%4];" \
                 : "=r"((r)[0]), "=r"((r)[1]), "=r"((r)[2]), "=r"((r)[3]) : "r"(addr))
#define LDSM_X4T(r, addr) \
    asm volatile("ldmatrix.sync.aligned.m8n8.x4.trans.shared.b16 {%0,%1,%2,%3}, [%4];" \
                 : "=r"((r)[0]), "=r"((r)[1]), "=r"((r)[2]), "=r"((r)[3]) : "r"(addr))

__device__ __forceinline__ void mma16816h(float* d, const uint32_t* a, const uint32_t* b) {
    asm volatile(
        "mma.sync.aligned.m16n8k16.row.col.f32.f16.f16.f32 "
        "{%0,%1,%2,%3}, {%4,%5,%6,%7}, {%8,%9}, {%0,%1,%2,%3};"
        : "+f"(d[0]), "+f"(d[1]), "+f"(d[2]), "+f"(d[3])
        : "r"(a[0]), "r"(a[1]), "r"(a[2]), "r"(a[3]), "r"(b[0]), "r"(b[1]));
}

__device__ __forceinline__ uint32_t h2u(__half2 h) {
    uint32_t u;
    __builtin_memcpy(&u, &h, 4);
    return u;
}

// ---------------------------------------------------------------------------
// 1. fused: weight prep fp16 (blocks 0..127) + x -> fp16 (rest)
// ---------------------------------------------------------------------------
__global__ void conv_prep(const float* __restrict__ x,
                          const float* __restrict__ Wl,
                          const float* __restrict__ Wr) {
    int tid = threadIdx.x;
    if (blockIdx.x < PREP_BLOCKS) {
        int idx = blockIdx.x * 256 + tid;        // 0..32767
        int m2 = idx >> 14;
        int rem = idx & 16383;
        float w = (m2 ? Wr : Wl)[rem];
        g_W[m2 * 16384 + rem] = __float2half_rn(w);
        return;
    }
    int i = ((int)blockIdx.x - PREP_BLOCKS) * 256 + tid;   // one 8-float chunk
    if (i >= N_NODES * D / 8) return;
    const float4* xs = reinterpret_cast<const float4*>(x) + i * 2;
    float4 a = xs[0], b = xs[1];
    uint4 o;
    o.x = h2u(__floats2half2_rn(a.x, a.y));
    o.y = h2u(__floats2half2_rn(a.z, a.w));
    o.z = h2u(__floats2half2_rn(b.x, b.y));
    o.w = h2u(__floats2half2_rn(b.z, b.w));
    reinterpret_cast<uint4*>(g_xh)[i] = o;
}

// ---------------------------------------------------------------------------
// 2. edge scatter: 16 lanes per edge (2 edges/warp). fp16 gather,
//    red.global.add.noftz.v4.f16x2 (LTS byte/op balanced).
// ---------------------------------------------------------------------------
__global__ void scatter_kernel(const int* __restrict__ ei) {
    int warp = (blockIdx.x * blockDim.x + threadIdx.x) >> 5;
    int lane = threadIdx.x & 31;
    int li = lane & 15;
    int e = warp * 2 + (lane >> 4);
    if (e >= N_EDGES) return;
    int src = ei[e];
    int dst = ei[N_EDGES + e];

    uint4 v = reinterpret_cast<const uint4*>(g_xh + (size_t)src * D)[li];
    __half* dptr = g_sumh + (size_t)dst * D + li * 8;
    asm volatile("red.global.add.noftz.v4.f16x2 [%0], {%1, %2, %3, %4};"
                 :: "l"(dptr), "r"(v.x), "r"(v.y), "r"(v.z), "r"(v.w)
                 : "memory");
    if (li == 0) atomicAdd(g_deg + dst, 1.0f);
}

// ---------------------------------------------------------------------------
// 3. fp16-HMMA GEMM: out = x_h + relu(mean@Wl + x@Wr + b)
//    2 MMAs/tile-step. A mats: 0 = mean (per-chunk), 1/2 = x chunk0/chunk1
//    (both kept resident; epilogue residual read from SMEM fp16 x).
//    B via cp.async.ca (L1-cacheable -> g_W L1-hot across CTAs).
//    Computes invd from g_deg (re-zeroes it); re-zeroes g_sumh after read.
//    64x128 tile/CTA, 62KB smem -> 3 CTAs/SM.
// ---------------------------------------------------------------------------
#define ASTR 72
#define BSTR 136
#define A_MAT_B (64 * ASTR * 2)       // 9216 B
#define B_MAT_B (64 * BSTR * 2)       // 17408 B
#define SM_A_B (3 * A_MAT_B)          // 27648 B (mean, x_c0, x_c1)
#define SM_B_B (2 * B_MAT_B)          // 34816 B
#define SMEM_TOTAL (SM_A_B + SM_B_B)  // 62464 B -> 3 CTAs/SM

__global__ __launch_bounds__(256, 3)
void gemm_mma(const float* __restrict__ bl,
              float* __restrict__ out) {
    extern __shared__ char sm[];
    const uint32_t sA = smem_u32(sm);
    const uint32_t sB = sA + SM_A_B;

    const int tid = threadIdx.x;
    const int lane = tid & 31;
    const int w = tid >> 5;
    const int m0 = blockIdx.x * 64;
    const int mrow0 = (w >> 1) * 16;
    const int ncol0 = (w & 1) * 64;

    // A-conversion map: 4 threads per row, 16 cols each
    const int cr = tid >> 2;
    const int cpart = tid & 3;
    const int crow = m0 + cr;
    const bool cvalid = crow < N_NODES;
    float invd = 1.0f;
    if (cvalid) {
        invd = 1.0f / fmaxf(g_deg[crow], 1.0f);
        if (cpart == 0) g_deg[crow] = 0.f;      // re-zero for next replay
    }

    float acc[8][4];
    #pragma unroll
    for (int nt = 0; nt < 8; nt++)
        #pragma unroll
        for (int q = 0; q < 4; q++) acc[nt][q] = 0.f;

    for (int c = 0; c < 2; c++) {
        const int k0 = c * 64;
        __syncthreads();    // previous chunk's MMAs done before smem overwrite

        // ---- B: 2 fp16 mats x 64k x 128n via cp.async.ca (L1-hot) ----
        #pragma unroll
        for (int i = 0; i < 8; i++) {
            int idx = tid + i * 256;          // 0..2047
            int mat = idx >> 10;
            int rem = idx & 1023;
            int r = rem >> 4, sg = rem & 15;
            uint32_t dst = sB + mat * B_MAT_B + r * (BSTR * 2) + sg * 16;
            const void* src = g_W + mat * 16384 + (k0 + r) * 128 + sg * 8;
            CP_ASYNC16CA(dst, src);
        }
        // ---- A x-mat for this chunk (kept resident; mat index 1+c) ----
        #pragma unroll
        for (int i = 0; i < 2; i++) {
            int idx = tid + i * 256;          // 0..511
            int r = idx >> 3, sg = idx & 7;
            int row = m0 + r;
            bool valid = row < N_NODES;
            uint32_t dst = sA + (1 + c) * A_MAT_B + r * (ASTR * 2) + sg * 16;
            const void* src = valid ? (const void*)(g_xh + (size_t)row * D + k0 + sg * 8)
                                    : (const void*)g_xh;
            CP_ASYNC16Z(dst, src, valid ? 16 : 0);
        }
        CP_COMMIT();

        // ---- A mat 0 (mean fp16): g_sumh * invd; re-zero after read ----
        {
            uint4* hp = cvalid
                ? reinterpret_cast<uint4*>(g_sumh + (size_t)crow * D + k0 + cpart * 16)
                : nullptr;
            uint4 u0 = cvalid ? hp[0] : make_uint4(0, 0, 0, 0);
            uint4 u1 = cvalid ? hp[1] : make_uint4(0, 0, 0, 0);
            uint32_t h2s[8] = {u0.x, u0.y, u0.z, u0.w, u1.x, u1.y, u1.z, u1.w};
            uint32_t mo[8];
            #pragma unroll
            for (int i = 0; i < 8; i++) {
                float2 f = __half22float2(*reinterpret_cast<__half2*>(&h2s[i]));
                mo[i] = h2u(__floats2half2_rn(f.x * invd, f.y * invd));
            }
            uint4* dm = reinterpret_cast<uint4*>(sm + 0 * A_MAT_B + cr * (ASTR * 2) + cpart * 32);
            dm[0] = make_uint4(mo[0], mo[1], mo[2], mo[3]);
            dm[1] = make_uint4(mo[4], mo[5], mo[6], mo[7]);
            if (cvalid) {
                hp[0] = make_uint4(0, 0, 0, 0);   // re-zero fp16 sums for next replay
                hp[1] = make_uint4(0, 0, 0, 0);
            }
        }
        CP_WAIT0();
        __syncthreads();

        // ---- MMA mainloop: 4 k16-steps, 2 fp16 MMAs per tile-pair ----
        #pragma unroll
        for (int ks = 0; ks < 4; ks++) {
            const int kk = ks * 16;
            uint32_t a[2][4];
            {
                uint32_t addr0 = sA + 0 * A_MAT_B
                               + (mrow0 + (lane & 15)) * (ASTR * 2)
                               + (kk + ((lane >> 4) * 8)) * 2;
                LDSM_X4(a[0], addr0);
                uint32_t addr1 = sA + (1 + c) * A_MAT_B
                               + (mrow0 + (lane & 15)) * (ASTR * 2)
                               + (kk + ((lane >> 4) * 8)) * 2;
                LDSM_X4(a[1], addr1);
            }
            #pragma unroll
            for (int np = 0; np < 4; np++) {
                const int ncol = ncol0 + np * 16;
                uint32_t b[2][4];
                #pragma unroll
                for (int mat = 0; mat < 2; mat++) {
                    int quad = lane >> 3;
                    uint32_t addr = sB + mat * B_MAT_B
                                  + (kk + (quad & 1) * 8 + (lane & 7)) * (BSTR * 2)
                                  + (ncol + (quad >> 1) * 8) * 2;
                    LDSM_X4T(b[mat], addr);
                }
                #pragma unroll
                for (int nt = 0; nt < 2; nt++) {
                    float* d = acc[np * 2 + nt];
                    mma16816h(d, a[0], b[0] + nt * 2);   // m * Wl
                    mma16816h(d, a[1], b[1] + nt * 2);   // x * Wr
                }
            }
        }
    }

    // ---- epilogue: out = x_h + relu(acc + b); residual from SMEM fp16 x ----
    const int rq = lane >> 2;
    const int cq = (lane & 3) * 2;
    const int xmat = 1 + (ncol0 >> 6);      // chunk holding cols ncol0..ncol0+63
    #pragma unroll
    for (int h = 0; h < 2; h++) {
        int rloc = mrow0 + h * 8 + rq;
        int row = m0 + rloc;
        if (row < N_NODES) {
            #pragma unroll
            for (int nt = 0; nt < 8; nt++) {
                int col = ncol0 + nt * 8 + cq;
                float d0 = acc[nt][h * 2 + 0];
                float d1 = acc[nt][h * 2 + 1];
                float2 bv = *reinterpret_cast<const float2*>(bl + col);
                __half2 xh = *reinterpret_cast<const __half2*>(
                    sm + xmat * A_MAT_B + rloc * (ASTR * 2) + (col & 63) * 2);
                float2 xv = __half22float2(xh);
                float2 o;
                o.x = xv.x + fmaxf(d0 + bv.x, 0.f);
                o.y = xv.y + fmaxf(d1 + bv.y, 0.f);
                *reinterpret_cast<float2*>(out + (size_t)row * D + col) = o;
            }
        }
    }
}

// ---------------------------------------------------------------------------
// launch
// ---------------------------------------------------------------------------
extern "C" void kernel_launch(void* const* d_in, const int* in_sizes, int n_in,
                              void* d_out, int out_size) {
    const float* x  = (const float*)d_in[0];
    const int*   ei = (const int*)d_in[1];
    const float* Wl = (const float*)d_in[2];
    const float* bl = (const float*)d_in[3];
    const float* Wr = (const float*)d_in[4];
    float* out = (float*)d_out;
    (void)in_sizes; (void)n_in; (void)out_size;

    // 1. fused weight prep (fp16) + x->fp16 conversion
    conv_prep<<<PREP_BLOCKS + XCONV_BLOCKS, 256>>>(x, Wl, Wr);

    // 2. edge scatter: fp16 gather + fp16 v4 red (g_sumh zeroed by prev gemm)
    {
        int warps = (N_EDGES + 1) / 2;               // 312500
        int blocks = (warps * 32 + 255) / 256;       // 39063
        scatter_kernel<<<blocks, 256>>>(ei);
    }

    // 3. fp16-HMMA dual GEMM + bias + relu + residual (SMEM fp16 residual)
    //    (computes invd, re-zeroes g_deg and g_sumh)
    cudaFuncSetAttribute(gemm_mma, cudaFuncAttributeMaxDynamicSharedMemorySize,
                         SMEM_TOTAL);
    gemm_mma<<<(N_NODES + 63) / 64, 256, SMEM_TOTAL>>>(bl, out);
}